// round 7
// baseline (speedup 1.0000x reference)
#include <cuda_runtime.h>
#include <cuda_fp16.h>
#include <cstdint>

// Inputs:
//  d_in[0] pts            float32  [N_PTS, 3]
//  d_in[1] p2v_idx        int32    [N_PTS]
//  d_in[2] embeddings     float32  [N_EMB, 16]
//  d_in[3] center_points  float32  [N_VOX, 3]
//  d_in[4] center2corner  int32    [N_VOX, 8]
//  d_in[5] voxel_size     float32  [1]
// Output: float32 [N_PTS, 16]
//
// Voxel-grouped execution: points sharing a voxel gather the SAME 8 embedding
// rows (avg 4 pts/voxel). Preprocess: histogram -> scan -> scatter point ids
// by voxel. Main: one quad per voxel loads rows once, loops its points.
// fp16 emb table (rel_err ~2e-4), padded cp4/pts4 tables.

#define N_EMB_MAX 1000000
#define N_VOX_MAX 500000
#define N_PTS_MAX 2000000
#define SCAN_BLK  1024

__device__ __align__(16) __half  g_emb_h[N_EMB_MAX * 16];   // 32 MB
__device__ __align__(16) float4  g_cp4[N_VOX_MAX];          // 8 MB
__device__ __align__(16) float4  g_pts4[N_PTS_MAX];         // 32 MB
__device__ int g_hist[N_VOX_MAX];                           // counts -> cursor
__device__ int g_off[N_VOX_MAX];                            // exclusive offsets
__device__ int g_blocksums[SCAN_BLK];
__device__ int g_plist[N_PTS_MAX];                          // voxel-sorted ids

// ---- cache-hint helpers ----
__device__ __forceinline__ uint64_t make_evict_last_policy() {
    uint64_t pol;
    asm("createpolicy.fractional.L2::evict_last.b64 %0, 1.0;" : "=l"(pol));
    return pol;
}
__device__ __forceinline__ uint2 ldg_last_u2(const void* p, uint64_t pol) {
    uint2 v;
    asm volatile("ld.global.nc.L2::cache_hint.v2.b32 {%0,%1}, [%2], %3;"
                 : "=r"(v.x), "=r"(v.y) : "l"(p), "l"(pol));
    return v;
}
__device__ __forceinline__ float4 ldg_last_f4(const float4* p, uint64_t pol) {
    float4 v;
    asm volatile("ld.global.nc.L2::cache_hint.v4.f32 {%0,%1,%2,%3}, [%4], %5;"
                 : "=f"(v.x), "=f"(v.y), "=f"(v.z), "=f"(v.w)
                 : "l"(p), "l"(pol));
    return v;
}
__device__ __forceinline__ void ldg_last_i8(const int* p, int* o) {
    asm volatile("ld.global.nc.L2::evict_last.v8.b32 "
                 "{%0,%1,%2,%3,%4,%5,%6,%7}, [%8];"
                 : "=r"(o[0]), "=r"(o[1]), "=r"(o[2]), "=r"(o[3]),
                   "=r"(o[4]), "=r"(o[5]), "=r"(o[6]), "=r"(o[7])
                 : "l"(p));
}
__device__ __forceinline__ float4 ldg_stream_f4(const float4* p) {
    float4 v;
    asm volatile("ld.global.cs.v4.f32 {%0,%1,%2,%3}, [%4];"
                 : "=f"(v.x), "=f"(v.y), "=f"(v.z), "=f"(v.w) : "l"(p));
    return v;
}
__device__ __forceinline__ float ldg_stream_f(const float* p) {
    float v;
    asm volatile("ld.global.cs.f32 %0, [%1];" : "=f"(v) : "l"(p));
    return v;
}
__device__ __forceinline__ int ldg_stream_i(const int* p) {
    int v;
    asm volatile("ld.global.cs.s32 %0, [%1];" : "=r"(v) : "l"(p));
    return v;
}
__device__ __forceinline__ void stg_last_u4(void* p, uint4 v, uint64_t pol) {
    asm volatile("st.global.L2::cache_hint.v4.b32 [%0], {%1,%2,%3,%4}, %5;"
                 :: "l"(p), "r"(v.x), "r"(v.y), "r"(v.z), "r"(v.w), "l"(pol));
}
__device__ __forceinline__ void stg_last_f4(float4* p, float4 v, uint64_t pol) {
    asm volatile("st.global.L2::cache_hint.v4.f32 [%0], {%1,%2,%3,%4}, %5;"
                 :: "l"(p), "f"(v.x), "f"(v.y), "f"(v.z), "f"(v.w), "l"(pol));
}
__device__ __forceinline__ void stg_stream_f4(float4* p, float4 v) {
    asm volatile("st.global.cs.v4.f32 [%0], {%1,%2,%3,%4};"
                 :: "l"(p), "f"(v.x), "f"(v.y), "f"(v.z), "f"(v.w));
}

// ---- k1: merged table prep: emb->fp16, cp->f4 (+hist zero), pts->f4 ----
__global__ void convert_tables_kernel(const float* __restrict__ emb,
                                      const float* __restrict__ cp,
                                      const float* __restrict__ pts,
                                      int n8, int n_vox, int n_pts)
{
    int i = blockIdx.x * blockDim.x + threadIdx.x;
    uint64_t pol = make_evict_last_policy();
    if (i < n8) {
        const float4* src = reinterpret_cast<const float4*>(emb) + (size_t)i * 2;
        float4 a = ldg_stream_f4(&src[0]);
        float4 b = ldg_stream_f4(&src[1]);
        __half2 h0 = __floats2half2_rn(a.x, a.y);
        __half2 h1 = __floats2half2_rn(a.z, a.w);
        __half2 h2 = __floats2half2_rn(b.x, b.y);
        __half2 h3 = __floats2half2_rn(b.z, b.w);
        uint4 packed;
        packed.x = *reinterpret_cast<uint32_t*>(&h0);
        packed.y = *reinterpret_cast<uint32_t*>(&h1);
        packed.z = *reinterpret_cast<uint32_t*>(&h2);
        packed.w = *reinterpret_cast<uint32_t*>(&h3);
        stg_last_u4(reinterpret_cast<uint4*>(g_emb_h) + i, packed, pol);
        return;
    }
    int j = i - n8;
    if (j < n_vox) {
        float x = ldg_stream_f(&cp[3 * j + 0]);
        float y = ldg_stream_f(&cp[3 * j + 1]);
        float z = ldg_stream_f(&cp[3 * j + 2]);
        stg_last_f4(&g_cp4[j], make_float4(x, y, z, 0.0f), pol);
        g_hist[j] = 0;
        return;
    }
    int k = j - n_vox;
    if (k < n_pts) {
        float x = ldg_stream_f(&pts[3 * k + 0]);
        float y = ldg_stream_f(&pts[3 * k + 1]);
        float z = ldg_stream_f(&pts[3 * k + 2]);
        g_pts4[k] = make_float4(x, y, z, 0.0f);
    }
}

// ---- k2: histogram of p2v ----
__global__ void hist_kernel(const int* __restrict__ p2v, int n_pts)
{
    int i = blockIdx.x * blockDim.x + threadIdx.x;
    if (i >= n_pts) return;
    atomicAdd(&g_hist[ldg_stream_i(&p2v[i])], 1);
}

// ---- k3: per-block exclusive scan of hist -> g_off, block totals ----
__global__ void scan_block_kernel(int n_vox)
{
    __shared__ int s[SCAN_BLK];
    int t = threadIdx.x;
    int i = blockIdx.x * SCAN_BLK + t;
    int v = (i < n_vox) ? g_hist[i] : 0;
    s[t] = v;
    __syncthreads();
    #pragma unroll
    for (int off = 1; off < SCAN_BLK; off <<= 1) {
        int x = (t >= off) ? s[t - off] : 0;
        __syncthreads();
        s[t] += x;
        __syncthreads();
    }
    if (i < n_vox) g_off[i] = s[t] - v;          // exclusive within block
    if (t == SCAN_BLK - 1) g_blocksums[blockIdx.x] = s[t];
}

// ---- k4: scan block totals (single block) ----
__global__ void scan_top_kernel(int nblocks)
{
    __shared__ int s[SCAN_BLK];
    int t = threadIdx.x;
    int v = (t < nblocks) ? g_blocksums[t] : 0;
    s[t] = v;
    __syncthreads();
    #pragma unroll
    for (int off = 1; off < SCAN_BLK; off <<= 1) {
        int x = (t >= off) ? s[t - off] : 0;
        __syncthreads();
        s[t] += x;
        __syncthreads();
    }
    if (t < nblocks) g_blocksums[t] = s[t] - v;  // exclusive
}

// ---- k5: add block offsets; init cursor (g_hist) = final offsets ----
__global__ void scan_fix_kernel(int n_vox)
{
    int i = blockIdx.x * blockDim.x + threadIdx.x;
    if (i >= n_vox) return;
    int o = g_off[i] + g_blocksums[i / SCAN_BLK];
    g_off[i]  = o;
    g_hist[i] = o;   // cursor for scatter; after scatter, g_hist[v] = end(v)
}

// ---- k6: scatter point ids into voxel-sorted list ----
__global__ void scatter_kernel(const int* __restrict__ p2v, int n_pts)
{
    int i = blockIdx.x * blockDim.x + threadIdx.x;
    if (i >= n_pts) return;
    int v = ldg_stream_i(&p2v[i]);
    int pos = atomicAdd(&g_hist[v], 1);
    g_plist[pos] = i;
}

// ---- k7: main — one quad per voxel ----
__global__ void __launch_bounds__(256, 4) voxel_interp_grouped_kernel(
    const int*    __restrict__ center2corner,
    const float*  __restrict__ voxel_size,
    float*        __restrict__ out,
    int n_vox)
{
    int tid = blockIdx.x * blockDim.x + threadIdx.x;
    int v   = tid >> 2;
    int sub = tid & 3;
    if (v >= n_vox) return;

    int start = __ldg(&g_off[v]);
    int end   = __ldg(&g_hist[v]);   // cursor after scatter == start + count
    if (start >= end) return;

    uint64_t pol = make_evict_last_policy();

    int cidx[8];
    ldg_last_i8(center2corner + (size_t)v * 8, cidx);
    float4 cp = ldg_last_f4(&g_cp4[v], pol);

    // gather this voxel's 8 rows ONCE (this lane's 4 dims = 8B per row)
    uint2 r[8];
    #pragma unroll
    for (int c = 0; c < 8; ++c) {
        const char* rowp = reinterpret_cast<const char*>(g_emb_h)
                         + (size_t)cidx[c] * 32 + sub * 8;
        r[c] = ldg_last_u2(rowp, pol);
    }
    float2 e[8][2];
    #pragma unroll
    for (int c = 0; c < 8; ++c) {
        e[c][0] = __half22float2(*reinterpret_cast<__half2*>(&r[c].x));
        e[c][1] = __half22float2(*reinterpret_cast<__half2*>(&r[c].y));
    }

    float inv_vs = 1.0f / __ldg(&voxel_size[0]);

    for (int k = start; k < end; ++k) {
        int p = __ldg(&g_plist[k]);
        float4 P = ldg_stream_f4(&g_pts4[p]);
        float px = (P.x - cp.x) * inv_vs + 0.5f;
        float py = (P.y - cp.y) * inv_vs + 0.5f;
        float pz = (P.z - cp.z) * inv_vs + 0.5f;
        float wx[2] = {1.0f - px, px};
        float wy[2] = {1.0f - py, py};
        float wz[2] = {1.0f - pz, pz};

        float4 acc = make_float4(0.0f, 0.0f, 0.0f, 0.0f);
        #pragma unroll
        for (int c = 0; c < 8; ++c) {
            float w = wx[(c >> 2) & 1] * wy[(c >> 1) & 1] * wz[c & 1];
            acc.x = fmaf(w, e[c][0].x, acc.x);
            acc.y = fmaf(w, e[c][0].y, acc.y);
            acc.z = fmaf(w, e[c][1].x, acc.z);
            acc.w = fmaf(w, e[c][1].y, acc.w);
        }
        stg_stream_f4(reinterpret_cast<float4*>(out) + (size_t)p * 4 + sub, acc);
    }
}

extern "C" void kernel_launch(void* const* d_in, const int* in_sizes, int n_in,
                              void* d_out, int out_size)
{
    const float* pts            = (const float*)d_in[0];
    const int*   p2v_idx        = (const int*)  d_in[1];
    const float* embeddings     = (const float*)d_in[2];
    const float* center_points  = (const float*)d_in[3];
    const int*   center2corner  = (const int*)  d_in[4];
    const float* voxel_size     = (const float*)d_in[5];
    float*       out            = (float*)d_out;

    int n8    = in_sizes[2] / 8;
    int n_vox = in_sizes[3] / 3;
    int n_pts = in_sizes[0] / 3;

    int conv_threads = n8 + n_vox + n_pts;
    convert_tables_kernel<<<(conv_threads + 255) / 256, 256>>>(
        embeddings, center_points, pts, n8, n_vox, n_pts);

    hist_kernel<<<(n_pts + 255) / 256, 256>>>(p2v_idx, n_pts);

    int nblocks = (n_vox + SCAN_BLK - 1) / SCAN_BLK;   // <= 1024 for 500k
    scan_block_kernel<<<nblocks, SCAN_BLK>>>(n_vox);
    scan_top_kernel<<<1, SCAN_BLK>>>(nblocks);
    scan_fix_kernel<<<(n_vox + 255) / 256, 256>>>(n_vox);

    scatter_kernel<<<(n_pts + 255) / 256, 256>>>(p2v_idx, n_pts);

    int total_threads = n_vox * 4;
    voxel_interp_grouped_kernel<<<(total_threads + 255) / 256, 256>>>(
        center2corner, voxel_size, out, n_vox);
}

// round 8
// speedup vs baseline: 1.1816x; 1.1816x over previous
#include <cuda_runtime.h>
#include <cuda_fp16.h>
#include <cstdint>

// Inputs:
//  d_in[0] pts            float32  [N_PTS, 3]
//  d_in[1] p2v_idx        int32    [N_PTS]
//  d_in[2] embeddings     float32  [N_EMB, 16]
//  d_in[3] center_points  float32  [N_VOX, 3]
//  d_in[4] center2corner  int32    [N_VOX, 8]
//  d_in[5] voxel_size     float32  [1]
// Output: float32 [N_PTS, 16]
//
// Voxel-sorted uniform kernel: counting-sort points by voxel, then run the
// R6-style quad-per-point kernel over the sorted list. Same-voxel quads in a
// warp issue IDENTICAL addresses in the same load instruction -> L1 coalescing
// dedups them (emb wavefronts 8/pt -> ~2.75/pt) with no divergence and no
// extra instructions. fp16 emb table (rel_err ~2e-4 < 1e-3).

#define N_EMB_MAX 1000000
#define N_VOX_MAX 500000
#define N_PTS_MAX 2000000
#define SBLK      1024

__device__ __align__(16) __half g_emb_h[N_EMB_MAX * 16];  // 32 MB
__device__ __align__(16) float4 g_cp4[N_VOX_MAX];         // 8 MB
__device__ __align__(16) float4 g_pts4[N_PTS_MAX];        // 32 MB
__device__ int  g_hist[N_VOX_MAX];                        // counts -> cursor
__device__ int  g_off[N_VOX_MAX];                         // block-local scan
__device__ int  g_blocksums[SBLK];
__device__ __align__(8) int2 g_sorted[N_PTS_MAX];         // {point, voxel}

// ---- cache-hint helpers ----
__device__ __forceinline__ uint64_t make_evict_last_policy() {
    uint64_t pol;
    asm("createpolicy.fractional.L2::evict_last.b64 %0, 1.0;" : "=l"(pol));
    return pol;
}
__device__ __forceinline__ uint2 ldg_last_u2(const void* p, uint64_t pol) {
    uint2 v;
    asm volatile("ld.global.nc.L2::cache_hint.v2.b32 {%0,%1}, [%2], %3;"
                 : "=r"(v.x), "=r"(v.y) : "l"(p), "l"(pol));
    return v;
}
__device__ __forceinline__ float4 ldg_last_f4(const float4* p, uint64_t pol) {
    float4 v;
    asm volatile("ld.global.nc.L2::cache_hint.v4.f32 {%0,%1,%2,%3}, [%4], %5;"
                 : "=f"(v.x), "=f"(v.y), "=f"(v.z), "=f"(v.w)
                 : "l"(p), "l"(pol));
    return v;
}
__device__ __forceinline__ void ldg_last_i8(const int* p, int* o) {
    asm volatile("ld.global.nc.L2::evict_last.v8.b32 "
                 "{%0,%1,%2,%3,%4,%5,%6,%7}, [%8];"
                 : "=r"(o[0]), "=r"(o[1]), "=r"(o[2]), "=r"(o[3]),
                   "=r"(o[4]), "=r"(o[5]), "=r"(o[6]), "=r"(o[7])
                 : "l"(p));
}
__device__ __forceinline__ float4 ldg_stream_f4(const float4* p) {
    float4 v;
    asm volatile("ld.global.cs.v4.f32 {%0,%1,%2,%3}, [%4];"
                 : "=f"(v.x), "=f"(v.y), "=f"(v.z), "=f"(v.w) : "l"(p));
    return v;
}
__device__ __forceinline__ float ldg_stream_f(const float* p) {
    float v;
    asm volatile("ld.global.cs.f32 %0, [%1];" : "=f"(v) : "l"(p));
    return v;
}
__device__ __forceinline__ int ldg_stream_i(const int* p) {
    int v;
    asm volatile("ld.global.cs.s32 %0, [%1];" : "=r"(v) : "l"(p));
    return v;
}
__device__ __forceinline__ void stg_last_u4(void* p, uint4 v, uint64_t pol) {
    asm volatile("st.global.L2::cache_hint.v4.b32 [%0], {%1,%2,%3,%4}, %5;"
                 :: "l"(p), "r"(v.x), "r"(v.y), "r"(v.z), "r"(v.w), "l"(pol));
}
__device__ __forceinline__ void stg_last_f4(float4* p, float4 v, uint64_t pol) {
    asm volatile("st.global.L2::cache_hint.v4.f32 [%0], {%1,%2,%3,%4}, %5;"
                 :: "l"(p), "f"(v.x), "f"(v.y), "f"(v.z), "f"(v.w), "l"(pol));
}
__device__ __forceinline__ void stg_stream_f4(float4* p, float4 v) {
    asm volatile("st.global.cs.v4.f32 [%0], {%1,%2,%3,%4};"
                 :: "l"(p), "f"(v.x), "f"(v.y), "f"(v.z), "f"(v.w));
}

// ---- k1: table prep (emb fp16, cp4, pts4) + histogram (g_hist pre-zeroed) ----
__global__ void prep_kernel(const float* __restrict__ emb,
                            const float* __restrict__ cp,
                            const float* __restrict__ pts,
                            const int*   __restrict__ p2v,
                            int n8, int n_vox, int n_pts)
{
    int i = blockIdx.x * blockDim.x + threadIdx.x;
    uint64_t pol = make_evict_last_policy();
    if (i < n8) {
        const float4* src = reinterpret_cast<const float4*>(emb) + (size_t)i * 2;
        float4 a = ldg_stream_f4(&src[0]);
        float4 b = ldg_stream_f4(&src[1]);
        __half2 h0 = __floats2half2_rn(a.x, a.y);
        __half2 h1 = __floats2half2_rn(a.z, a.w);
        __half2 h2 = __floats2half2_rn(b.x, b.y);
        __half2 h3 = __floats2half2_rn(b.z, b.w);
        uint4 packed;
        packed.x = *reinterpret_cast<uint32_t*>(&h0);
        packed.y = *reinterpret_cast<uint32_t*>(&h1);
        packed.z = *reinterpret_cast<uint32_t*>(&h2);
        packed.w = *reinterpret_cast<uint32_t*>(&h3);
        stg_last_u4(reinterpret_cast<uint4*>(g_emb_h) + i, packed, pol);
        return;
    }
    int j = i - n8;
    if (j < n_vox) {
        float x = ldg_stream_f(&cp[3 * j + 0]);
        float y = ldg_stream_f(&cp[3 * j + 1]);
        float z = ldg_stream_f(&cp[3 * j + 2]);
        stg_last_f4(&g_cp4[j], make_float4(x, y, z, 0.0f), pol);
        return;
    }
    int k = j - n_vox;
    if (k < n_pts) {
        float x = ldg_stream_f(&pts[3 * k + 0]);
        float y = ldg_stream_f(&pts[3 * k + 1]);
        float z = ldg_stream_f(&pts[3 * k + 2]);
        g_pts4[k] = make_float4(x, y, z, 0.0f);
        return;
    }
    int m = k - n_pts;
    if (m < n_pts) {
        atomicAdd(&g_hist[ldg_stream_i(&p2v[m])], 1);
    }
}

// ---- k2: per-block exclusive scan (warp shuffle) ----
__global__ void scan_block_kernel(int n)
{
    __shared__ int wsum[SBLK / 32];
    int t = threadIdx.x;
    int g = blockIdx.x * SBLK + t;
    int lane = t & 31, wid = t >> 5;
    int x = (g < n) ? g_hist[g] : 0;
    int v = x;
    #pragma unroll
    for (int o = 1; o < 32; o <<= 1) {
        int y = __shfl_up_sync(0xffffffffu, v, o);
        if (lane >= o) v += y;
    }
    if (lane == 31) wsum[wid] = v;
    __syncthreads();
    if (wid == 0) {
        int s = (lane < SBLK / 32) ? wsum[lane] : 0;
        #pragma unroll
        for (int o = 1; o < 32; o <<= 1) {
            int y = __shfl_up_sync(0xffffffffu, s, o);
            if (lane >= o) s += y;
        }
        if (lane < SBLK / 32) wsum[lane] = s;   // inclusive warp-sum scan
    }
    __syncthreads();
    int excl = v - x + (wid > 0 ? wsum[wid - 1] : 0);
    if (g < n) g_off[g] = excl;
    if (t == SBLK - 1) g_blocksums[blockIdx.x] = excl + x;
}

// ---- k3: scan block totals in place (exclusive), 1 block ----
__global__ void scan_top_kernel(int nb)
{
    __shared__ int wsum[SBLK / 32];
    int t = threadIdx.x;
    int lane = t & 31, wid = t >> 5;
    int x = (t < nb) ? g_blocksums[t] : 0;
    int v = x;
    #pragma unroll
    for (int o = 1; o < 32; o <<= 1) {
        int y = __shfl_up_sync(0xffffffffu, v, o);
        if (lane >= o) v += y;
    }
    if (lane == 31) wsum[wid] = v;
    __syncthreads();
    if (wid == 0) {
        int s = (lane < SBLK / 32) ? wsum[lane] : 0;
        #pragma unroll
        for (int o = 1; o < 32; o <<= 1) {
            int y = __shfl_up_sync(0xffffffffu, s, o);
            if (lane >= o) s += y;
        }
        if (lane < SBLK / 32) wsum[lane] = s;
    }
    __syncthreads();
    if (t < nb) g_blocksums[t] = v - x + (wid > 0 ? wsum[wid - 1] : 0);
}

// ---- k4: cursor = global exclusive offset ----
__global__ void scan_fix_kernel(int n)
{
    int i = blockIdx.x * blockDim.x + threadIdx.x;
    if (i >= n) return;
    g_hist[i] = g_off[i] + g_blocksums[i / SBLK];
}

// ---- k5: scatter {point, voxel} into voxel-sorted list ----
__global__ void scatter_kernel(const int* __restrict__ p2v, int n_pts)
{
    int i = blockIdx.x * blockDim.x + threadIdx.x;
    if (i >= n_pts) return;
    int v = ldg_stream_i(&p2v[i]);
    int pos = atomicAdd(&g_hist[v], 1);
    g_sorted[pos] = make_int2(i, v);
}

// ---- k6: main — quad per sorted point (uniform control flow) ----
__global__ void __launch_bounds__(256) voxel_interp_sorted_kernel(
    const int*    __restrict__ center2corner,
    const float*  __restrict__ voxel_size,
    float*        __restrict__ out,
    int n_pts)
{
    int tid = blockIdx.x * blockDim.x + threadIdx.x;
    int i   = tid >> 2;
    int sub = tid & 3;
    if (i >= n_pts) return;

    uint64_t pol = make_evict_last_policy();

    int2 pv = __ldg(&g_sorted[i]);   // coalesced: warp = 8 int2 = 64B
    int p = pv.x;
    int v = pv.y;

    // same-voxel quads in this warp issue identical addresses below ->
    // L1 dedups to ~2.75 distinct lines per warp instruction.
    int cidx[8];
    ldg_last_i8(center2corner + (size_t)v * 8, cidx);
    float4 cp = ldg_last_f4(&g_cp4[v], pol);
    float4 P  = ldg_stream_f4(&g_pts4[p]);

    uint2 r[8];
    #pragma unroll
    for (int c = 0; c < 8; ++c) {
        const char* rowp = reinterpret_cast<const char*>(g_emb_h)
                         + (size_t)cidx[c] * 32 + sub * 8;
        r[c] = ldg_last_u2(rowp, pol);
    }

    float inv_vs = 1.0f / __ldg(&voxel_size[0]);
    float px = (P.x - cp.x) * inv_vs + 0.5f;
    float py = (P.y - cp.y) * inv_vs + 0.5f;
    float pz = (P.z - cp.z) * inv_vs + 0.5f;
    float wx[2] = {1.0f - px, px};
    float wy[2] = {1.0f - py, py};
    float wz[2] = {1.0f - pz, pz};

    float4 acc = make_float4(0.0f, 0.0f, 0.0f, 0.0f);
    #pragma unroll
    for (int c = 0; c < 8; ++c) {
        float w = wx[(c >> 2) & 1] * wy[(c >> 1) & 1] * wz[c & 1];
        float2 f01 = __half22float2(*reinterpret_cast<__half2*>(&r[c].x));
        float2 f23 = __half22float2(*reinterpret_cast<__half2*>(&r[c].y));
        acc.x = fmaf(w, f01.x, acc.x);
        acc.y = fmaf(w, f01.y, acc.y);
        acc.z = fmaf(w, f23.x, acc.z);
        acc.w = fmaf(w, f23.y, acc.w);
    }

    stg_stream_f4(reinterpret_cast<float4*>(out) + (size_t)p * 4 + sub, acc);
}

extern "C" void kernel_launch(void* const* d_in, const int* in_sizes, int n_in,
                              void* d_out, int out_size)
{
    const float* pts            = (const float*)d_in[0];
    const int*   p2v_idx        = (const int*)  d_in[1];
    const float* embeddings     = (const float*)d_in[2];
    const float* center_points  = (const float*)d_in[3];
    const int*   center2corner  = (const int*)  d_in[4];
    const float* voxel_size     = (const float*)d_in[5];
    float*       out            = (float*)d_out;

    int n8    = in_sizes[2] / 8;
    int n_vox = in_sizes[3] / 3;
    int n_pts = in_sizes[0] / 3;

    // zero histogram (async memset is graph-capturable; no allocation)
    void* hist_ptr = nullptr;
    cudaGetSymbolAddress(&hist_ptr, g_hist);
    cudaMemsetAsync(hist_ptr, 0, (size_t)n_vox * sizeof(int));

    int prep_threads = n8 + n_vox + 2 * n_pts;
    prep_kernel<<<(prep_threads + 255) / 256, 256>>>(
        embeddings, center_points, pts, p2v_idx, n8, n_vox, n_pts);

    int nblocks = (n_vox + SBLK - 1) / SBLK;   // 489 <= 1024
    scan_block_kernel<<<nblocks, SBLK>>>(n_vox);
    scan_top_kernel<<<1, SBLK>>>(nblocks);
    scan_fix_kernel<<<(n_vox + 255) / 256, 256>>>(n_vox);

    scatter_kernel<<<(n_pts + 255) / 256, 256>>>(p2v_idx, n_pts);

    int total_threads = n_pts * 4;
    voxel_interp_sorted_kernel<<<(total_threads + 255) / 256, 256>>>(
        center2corner, voxel_size, out, n_pts);
}

// round 9
// speedup vs baseline: 1.3162x; 1.1138x over previous
#include <cuda_runtime.h>
#include <cuda_fp16.h>
#include <cstdint>

// Inputs:
//  d_in[0] pts            float32  [N_PTS, 3]
//  d_in[1] p2v_idx        int32    [N_PTS]
//  d_in[2] embeddings     float32  [N_EMB, 16]
//  d_in[3] center_points  float32  [N_VOX, 3]
//  d_in[4] center2corner  int32    [N_VOX, 8]
//  d_in[5] voxel_size     float32  [1]
// Output: float32 [N_PTS, 16]
//
// Voxel-grouped main kernel with per-voxel linked lists (atomicExch build, no
// sort chain). Each quad loads its voxel's 8 fp16 rows ONCE (structural 4x
// dedup of the dominant gather) and iterates the voxel's points. fp16 emb
// (rel_err ~2e-4 < 1e-3). 4 graph nodes total.

#define N_EMB_MAX 1000000
#define N_VOX_MAX 500000
#define N_PTS_MAX 2000000

__device__ __align__(16) __half g_emb_h[N_EMB_MAX * 16];  // 32 MB
__device__ __align__(16) float4 g_cp4[N_VOX_MAX];         // 8 MB
__device__ __align__(16) float4 g_pts4[N_PTS_MAX];        // 32 MB
__device__ int g_head[N_VOX_MAX];                         // 2 MB (memset -1)
__device__ int g_next[N_PTS_MAX];                         // 8 MB

// ---- cache-hint helpers ----
__device__ __forceinline__ uint64_t make_evict_last_policy() {
    uint64_t pol;
    asm("createpolicy.fractional.L2::evict_last.b64 %0, 1.0;" : "=l"(pol));
    return pol;
}
__device__ __forceinline__ uint2 ldg_last_u2(const void* p, uint64_t pol) {
    uint2 v;
    asm volatile("ld.global.nc.L2::cache_hint.v2.b32 {%0,%1}, [%2], %3;"
                 : "=r"(v.x), "=r"(v.y) : "l"(p), "l"(pol));
    return v;
}
__device__ __forceinline__ float4 ldg_last_f4(const float4* p, uint64_t pol) {
    float4 v;
    asm volatile("ld.global.nc.L2::cache_hint.v4.f32 {%0,%1,%2,%3}, [%4], %5;"
                 : "=f"(v.x), "=f"(v.y), "=f"(v.z), "=f"(v.w)
                 : "l"(p), "l"(pol));
    return v;
}
__device__ __forceinline__ void ldg_last_i8(const int* p, int* o) {
    asm volatile("ld.global.nc.L2::evict_last.v8.b32 "
                 "{%0,%1,%2,%3,%4,%5,%6,%7}, [%8];"
                 : "=r"(o[0]), "=r"(o[1]), "=r"(o[2]), "=r"(o[3]),
                   "=r"(o[4]), "=r"(o[5]), "=r"(o[6]), "=r"(o[7])
                 : "l"(p));
}
__device__ __forceinline__ float4 ldg_stream_f4(const float4* p) {
    float4 v;
    asm volatile("ld.global.cs.v4.f32 {%0,%1,%2,%3}, [%4];"
                 : "=f"(v.x), "=f"(v.y), "=f"(v.z), "=f"(v.w) : "l"(p));
    return v;
}
__device__ __forceinline__ float ldg_stream_f(const float* p) {
    float v;
    asm volatile("ld.global.cs.f32 %0, [%1];" : "=f"(v) : "l"(p));
    return v;
}
__device__ __forceinline__ int ldg_stream_i(const int* p) {
    int v;
    asm volatile("ld.global.cs.s32 %0, [%1];" : "=r"(v) : "l"(p));
    return v;
}
__device__ __forceinline__ void stg_last_u4(void* p, uint4 v, uint64_t pol) {
    asm volatile("st.global.L2::cache_hint.v4.b32 [%0], {%1,%2,%3,%4}, %5;"
                 :: "l"(p), "r"(v.x), "r"(v.y), "r"(v.z), "r"(v.w), "l"(pol));
}
__device__ __forceinline__ void stg_last_f4(float4* p, float4 v, uint64_t pol) {
    asm volatile("st.global.L2::cache_hint.v4.f32 [%0], {%1,%2,%3,%4}, %5;"
                 :: "l"(p), "f"(v.x), "f"(v.y), "f"(v.z), "f"(v.w), "l"(pol));
}
__device__ __forceinline__ void stg_stream_f4(float4* p, float4 v) {
    asm volatile("st.global.cs.v4.f32 [%0], {%1,%2,%3,%4};"
                 :: "l"(p), "f"(v.x), "f"(v.y), "f"(v.z), "f"(v.w));
}

// ---- k1: table prep: emb fp32->fp16, cp->float4 ----
__global__ void prep_kernel(const float* __restrict__ emb,
                            const float* __restrict__ cp,
                            int n8, int n_vox)
{
    int i = blockIdx.x * blockDim.x + threadIdx.x;
    uint64_t pol = make_evict_last_policy();
    if (i < n8) {
        const float4* src = reinterpret_cast<const float4*>(emb) + (size_t)i * 2;
        float4 a = ldg_stream_f4(&src[0]);
        float4 b = ldg_stream_f4(&src[1]);
        __half2 h0 = __floats2half2_rn(a.x, a.y);
        __half2 h1 = __floats2half2_rn(a.z, a.w);
        __half2 h2 = __floats2half2_rn(b.x, b.y);
        __half2 h3 = __floats2half2_rn(b.z, b.w);
        uint4 packed;
        packed.x = *reinterpret_cast<uint32_t*>(&h0);
        packed.y = *reinterpret_cast<uint32_t*>(&h1);
        packed.z = *reinterpret_cast<uint32_t*>(&h2);
        packed.w = *reinterpret_cast<uint32_t*>(&h3);
        stg_last_u4(reinterpret_cast<uint4*>(g_emb_h) + i, packed, pol);
        return;
    }
    int j = i - n8;
    if (j < n_vox) {
        float x = ldg_stream_f(&cp[3 * j + 0]);
        float y = ldg_stream_f(&cp[3 * j + 1]);
        float z = ldg_stream_f(&cp[3 * j + 2]);
        stg_last_f4(&g_cp4[j], make_float4(x, y, z, 0.0f), pol);
    }
}

// ---- k2: build per-voxel linked lists + pad pts to float4 ----
__global__ void build_lists_kernel(const int*   __restrict__ p2v,
                                   const float* __restrict__ pts,
                                   int n_pts)
{
    int i = blockIdx.x * blockDim.x + threadIdx.x;
    if (i >= n_pts) return;
    float x = ldg_stream_f(&pts[3 * i + 0]);
    float y = ldg_stream_f(&pts[3 * i + 1]);
    float z = ldg_stream_f(&pts[3 * i + 2]);
    g_pts4[i] = make_float4(x, y, z, 0.0f);
    int v = ldg_stream_i(&p2v[i]);
    g_next[i] = atomicExch(&g_head[v], i);
}

// ---- k3: main — quad per voxel, walk its point list ----
__global__ void __launch_bounds__(256) voxel_interp_grouped_kernel(
    const int*    __restrict__ center2corner,
    const float*  __restrict__ voxel_size,
    float*        __restrict__ out,
    int n_vox)
{
    int tid = blockIdx.x * blockDim.x + threadIdx.x;
    int v   = tid >> 2;
    int sub = tid & 3;
    if (v >= n_vox) return;

    int p = __ldg(&g_head[v]);
    if (p < 0) return;

    uint64_t pol = make_evict_last_policy();

    // per-voxel loads: ONCE regardless of point count
    int cidx[8];
    ldg_last_i8(center2corner + (size_t)v * 8, cidx);
    float4 cp = ldg_last_f4(&g_cp4[v], pol);

    uint2 r[8];   // raw fp16 rows: this lane's 4 dims per corner (16 regs)
    #pragma unroll
    for (int c = 0; c < 8; ++c) {
        const char* rowp = reinterpret_cast<const char*>(g_emb_h)
                         + (size_t)cidx[c] * 32 + sub * 8;
        r[c] = ldg_last_u2(rowp, pol);
    }

    float inv_vs = 1.0f / __ldg(&voxel_size[0]);

    while (p >= 0) {
        float4 P = ldg_stream_f4(&g_pts4[p]);
        int pn = __ldg(&g_next[p]);    // prefetch next link early

        float px = (P.x - cp.x) * inv_vs + 0.5f;
        float py = (P.y - cp.y) * inv_vs + 0.5f;
        float pz = (P.z - cp.z) * inv_vs + 0.5f;
        float wx[2] = {1.0f - px, px};
        float wy[2] = {1.0f - py, py};
        float wz[2] = {1.0f - pz, pz};

        float4 acc = make_float4(0.0f, 0.0f, 0.0f, 0.0f);
        #pragma unroll
        for (int c = 0; c < 8; ++c) {
            // corner c (meshgrid ij): bit2 -> x, bit1 -> y, bit0 -> z
            float w = wx[(c >> 2) & 1] * wy[(c >> 1) & 1] * wz[c & 1];
            float2 f01 = __half22float2(*reinterpret_cast<const __half2*>(&r[c].x));
            float2 f23 = __half22float2(*reinterpret_cast<const __half2*>(&r[c].y));
            acc.x = fmaf(w, f01.x, acc.x);
            acc.y = fmaf(w, f01.y, acc.y);
            acc.z = fmaf(w, f23.x, acc.z);
            acc.w = fmaf(w, f23.y, acc.w);
        }
        stg_stream_f4(reinterpret_cast<float4*>(out) + (size_t)p * 4 + sub, acc);
        p = pn;
    }
}

extern "C" void kernel_launch(void* const* d_in, const int* in_sizes, int n_in,
                              void* d_out, int out_size)
{
    const float* pts            = (const float*)d_in[0];
    const int*   p2v_idx        = (const int*)  d_in[1];
    const float* embeddings     = (const float*)d_in[2];
    const float* center_points  = (const float*)d_in[3];
    const int*   center2corner  = (const int*)  d_in[4];
    const float* voxel_size     = (const float*)d_in[5];
    float*       out            = (float*)d_out;

    int n8    = in_sizes[2] / 8;   // emb chunks of 8 floats
    int n_vox = in_sizes[3] / 3;
    int n_pts = in_sizes[0] / 3;

    // node 1: head = -1
    void* head_ptr = nullptr;
    cudaGetSymbolAddress(&head_ptr, g_head);
    cudaMemsetAsync(head_ptr, 0xFF, (size_t)n_vox * sizeof(int));

    // node 2: tables
    int prep_threads = n8 + n_vox;
    prep_kernel<<<(prep_threads + 255) / 256, 256>>>(
        embeddings, center_points, n8, n_vox);

    // node 3: linked lists + pts pad
    build_lists_kernel<<<(n_pts + 255) / 256, 256>>>(p2v_idx, pts, n_pts);

    // node 4: main
    int total_threads = n_vox * 4;
    voxel_interp_grouped_kernel<<<(total_threads + 255) / 256, 256>>>(
        center2corner, voxel_size, out, n_vox);
}